// round 3
// baseline (speedup 1.0000x reference)
#include <cuda_runtime.h>
#include <math.h>

// Problem constants
#define T_LEN   512
#define B_SZ    128
#define H_SZ    1024
#define NIN     128
#define NOUT    128
#define ALPHA_F 0.25f
#define LEAK_F  0.75f           // 1 - alpha
#define NSCALE  0.025f          // SIGMA_NEU * sqrt(alpha) = 0.05 * 0.5
#define GRID_RNN 128

// ---------------- scratch (device globals: no allocation allowed) ----------
__device__ float g_c[(size_t)T_LEN * B_SZ * H_SZ];   // alpha*(xW_in+b_in+b_hh)+noise, [T,B,H]
__device__ float g_h[B_SZ * H_SZ];                   // current hidden
__device__ float g_a[B_SZ * H_SZ];                   // tanh(current hidden)
__device__ float g_p[4 * B_SZ * H_SZ];               // split-K partials
__device__ unsigned g_bar_count;
__device__ unsigned g_bar_release;

// ---------------- init: h, tanh(h), barrier state ---------------------------
__global__ void init_kernel(const float* __restrict__ hidden) {
    int i = blockIdx.x * blockDim.x + threadIdx.x;
    if (i == 0) { g_bar_count = 0u; g_bar_release = 0u; }
    if (i < B_SZ * H_SZ) {
        float h = hidden[i];
        g_h[i] = h;
        g_a[i] = tanhf(h);
    }
}

// ---------------- pre: c[t,b,h] = a*(x@Win^T + b_in + b_hh) + 0.025*noise ---
// GEMM [65536 x 128] @ [128 x 1024], rows r = t*128 + b (matches noise layout)
__global__ void __launch_bounds__(256) pre_kernel(
    const float* __restrict__ x,        // [B,T,NIN]
    const float* __restrict__ noise,    // [T,B,H]
    const float* __restrict__ w_in,     // [H,NIN]
    const float* __restrict__ b_in,     // [H]
    const float* __restrict__ b_hh)     // [H]
{
    __shared__ float As[16][68];
    __shared__ float Bs[16][68];
    int tid = threadIdx.x;
    int tr = tid >> 4, tc = tid & 15;
    int lr = tid >> 2, lk = (tid & 3) * 4;
    int r0 = blockIdx.x * 64;
    int c0 = blockIdx.y * 64;
    float acc[4][4] = {};

    int rA = r0 + lr;
    int tt = rA >> 7;          // r / 128
    int bb = rA & 127;         // r % 128
    const float* arow = x + ((size_t)bb * T_LEN + tt) * NIN;
    const float* brow = w_in + (size_t)(c0 + lr) * NIN;

    for (int ko = 0; ko < NIN; ko += 16) {
        float4 av = *(const float4*)(arow + ko + lk);
        float4 bv = *(const float4*)(brow + ko + lk);
        __syncthreads();
        As[lk + 0][lr] = av.x; As[lk + 1][lr] = av.y;
        As[lk + 2][lr] = av.z; As[lk + 3][lr] = av.w;
        Bs[lk + 0][lr] = bv.x; Bs[lk + 1][lr] = bv.y;
        Bs[lk + 2][lr] = bv.z; Bs[lk + 3][lr] = bv.w;
        __syncthreads();
        #pragma unroll
        for (int kk = 0; kk < 16; kk++) {
            float a[4], b[4];
            *(float4*)a = *(float4*)&As[kk][tr * 4];
            *(float4*)b = *(float4*)&Bs[kk][tc * 4];
            #pragma unroll
            for (int i = 0; i < 4; i++)
                #pragma unroll
                for (int j = 0; j < 4; j++)
                    acc[i][j] = fmaf(a[i], b[j], acc[i][j]);
        }
    }

    int c = c0 + tc * 4;
    float bi0 = b_in[c + 0] + b_hh[c + 0];
    float bi1 = b_in[c + 1] + b_hh[c + 1];
    float bi2 = b_in[c + 2] + b_hh[c + 2];
    float bi3 = b_in[c + 3] + b_hh[c + 3];
    #pragma unroll
    for (int i = 0; i < 4; i++) {
        int r = r0 + tr * 4 + i;
        size_t off = (size_t)r * H_SZ + c;
        float4 nv = *(const float4*)(noise + off);
        float4 v;
        v.x = ALPHA_F * (acc[i][0] + bi0) + NSCALE * nv.x;
        v.y = ALPHA_F * (acc[i][1] + bi1) + NSCALE * nv.y;
        v.z = ALPHA_F * (acc[i][2] + bi2) + NSCALE * nv.z;
        v.w = ALPHA_F * (acc[i][3] + bi3) + NSCALE * nv.w;
        *(float4*)(g_c + off) = v;
    }
}

// ---------------- grid barrier (cumulative-count, sense-free) ---------------
__device__ __forceinline__ void grid_bar(unsigned target) {
    __syncthreads();
    if (threadIdx.x == 0) {
        __threadfence();
        unsigned arrived = atomicAdd(&g_bar_count, 1u) + 1u;
        if (arrived == target * (unsigned)GRID_RNN) {
            __threadfence();
            atomicExch(&g_bar_release, target);
        } else {
            while (*(volatile unsigned*)&g_bar_release < target) {
                __nanosleep(64);
            }
        }
        __threadfence();
    }
    __syncthreads();
}

// ---------------- recurrent persistent kernel --------------------------------
// 128 CTAs = 2 b-tiles x 16 h-tiles x 4 k-splits. Per step:
//   phase G: partial tile (64x64 over K=256) of tanh(h) @ Whh^T -> g_p
//   barrier
//   phase U: each CTA owns 1024 elements: h' = 0.75h + 0.25*sum(partials) + c[t]
//            write g_h, g_a=tanh(h'), hidden_list[b,t,:], (h_final at t=511)
//   barrier
__global__ void __launch_bounds__(256) rnn_kernel(
    float* __restrict__ hid_list,       // [B,T,H] section of d_out
    float* __restrict__ h_final,        // [B,H]   section of d_out
    const float* __restrict__ w_hh)     // [H,H]
{
    __shared__ float As[16][68];
    __shared__ float Bs[16][68];
    int cta = blockIdx.x;
    int ks = cta & 3;
    int bt = (cta >> 2) & 1;
    int ht = cta >> 3;
    int tid = threadIdx.x;
    int tr = tid >> 4, tc = tid & 15;
    int lr = tid >> 2, lk = (tid & 3) * 4;
    int r0 = bt * 64, c0 = ht * 64, k0 = ks * 256;

    const float* arow = g_a + (size_t)(r0 + lr) * H_SZ;
    const float* brow = w_hh + (size_t)(c0 + lr) * H_SZ;
    float* pout = g_p + (size_t)ks * (B_SZ * H_SZ);

    int e  = cta * 1024 + tid * 4;      // update-phase element base
    int eb = e >> 10;                   // batch index
    int eh = e & 1023;                  // hidden index
    unsigned epoch = 0;

    for (int t = 0; t < T_LEN; t++) {
        // ---- phase G: split-K GEMM partial ----
        float acc[4][4] = {};
        for (int ko = k0; ko < k0 + 256; ko += 16) {
            float4 av = *(const float4*)(arow + ko + lk);
            float4 bv = *(const float4*)(brow + ko + lk);
            __syncthreads();
            As[lk + 0][lr] = av.x; As[lk + 1][lr] = av.y;
            As[lk + 2][lr] = av.z; As[lk + 3][lr] = av.w;
            Bs[lk + 0][lr] = bv.x; Bs[lk + 1][lr] = bv.y;
            Bs[lk + 2][lr] = bv.z; Bs[lk + 3][lr] = bv.w;
            __syncthreads();
            #pragma unroll
            for (int kk = 0; kk < 16; kk++) {
                float a[4], b[4];
                *(float4*)a = *(float4*)&As[kk][tr * 4];
                *(float4*)b = *(float4*)&Bs[kk][tc * 4];
                #pragma unroll
                for (int i = 0; i < 4; i++)
                    #pragma unroll
                    for (int j = 0; j < 4; j++)
                        acc[i][j] = fmaf(a[i], b[j], acc[i][j]);
            }
        }
        #pragma unroll
        for (int i = 0; i < 4; i++) {
            float4 v = make_float4(acc[i][0], acc[i][1], acc[i][2], acc[i][3]);
            *(float4*)(pout + (size_t)(r0 + tr * 4 + i) * H_SZ + c0 + tc * 4) = v;
        }

        grid_bar(++epoch);

        // ---- phase U: element-owner update ----
        {
            float4 p0 = *(const float4*)(g_p + e);
            float4 p1 = *(const float4*)(g_p + 1 * B_SZ * H_SZ + e);
            float4 p2 = *(const float4*)(g_p + 2 * B_SZ * H_SZ + e);
            float4 p3 = *(const float4*)(g_p + 3 * B_SZ * H_SZ + e);
            float4 hc = *(const float4*)(g_h + e);
            float4 cv = *(const float4*)(g_c + (size_t)t * (B_SZ * H_SZ) + e);
            float4 hn;
            hn.x = LEAK_F * hc.x + ALPHA_F * (p0.x + p1.x + p2.x + p3.x) + cv.x;
            hn.y = LEAK_F * hc.y + ALPHA_F * (p0.y + p1.y + p2.y + p3.y) + cv.y;
            hn.z = LEAK_F * hc.z + ALPHA_F * (p0.z + p1.z + p2.z + p3.z) + cv.z;
            hn.w = LEAK_F * hc.w + ALPHA_F * (p0.w + p1.w + p2.w + p3.w) + cv.w;
            *(float4*)(g_h + e) = hn;
            float4 an = make_float4(tanhf(hn.x), tanhf(hn.y), tanhf(hn.z), tanhf(hn.w));
            *(float4*)(g_a + e) = an;
            *(float4*)(hid_list + ((size_t)eb * T_LEN + t) * H_SZ + eh) = hn;
            if (t == T_LEN - 1) {
                *(float4*)(h_final + e) = hn;
            }
        }

        grid_bar(++epoch);
    }
}

// ---------------- post: out[b,t,o] = clip(hid @ Wout^T + b_out) -------------
// GEMM [65536 x 1024] @ [1024 x 128]
__global__ void __launch_bounds__(256) post_kernel(
    const float* __restrict__ hid_list, // [B,T,H]  (rows q = b*T+t)
    const float* __restrict__ w_out,    // [NOUT,H]
    const float* __restrict__ b_out,    // [NOUT]
    float* __restrict__ out_list)       // [B,T,NOUT]
{
    __shared__ float As[16][68];
    __shared__ float Bs[16][68];
    int tid = threadIdx.x;
    int tr = tid >> 4, tc = tid & 15;
    int lr = tid >> 2, lk = (tid & 3) * 4;
    int r0 = blockIdx.x * 64;
    int c0 = blockIdx.y * 64;
    float acc[4][4] = {};

    const float* arow = hid_list + (size_t)(r0 + lr) * H_SZ;
    const float* brow = w_out + (size_t)(c0 + lr) * H_SZ;

    for (int ko = 0; ko < H_SZ; ko += 16) {
        float4 av = *(const float4*)(arow + ko + lk);
        float4 bv = *(const float4*)(brow + ko + lk);
        __syncthreads();
        As[lk + 0][lr] = av.x; As[lk + 1][lr] = av.y;
        As[lk + 2][lr] = av.z; As[lk + 3][lr] = av.w;
        Bs[lk + 0][lr] = bv.x; Bs[lk + 1][lr] = bv.y;
        Bs[lk + 2][lr] = bv.z; Bs[lk + 3][lr] = bv.w;
        __syncthreads();
        #pragma unroll
        for (int kk = 0; kk < 16; kk++) {
            float a[4], b[4];
            *(float4*)a = *(float4*)&As[kk][tr * 4];
            *(float4*)b = *(float4*)&Bs[kk][tc * 4];
            #pragma unroll
            for (int i = 0; i < 4; i++)
                #pragma unroll
                for (int j = 0; j < 4; j++)
                    acc[i][j] = fmaf(a[i], b[j], acc[i][j]);
        }
    }

    int c = c0 + tc * 4;
    float bo0 = b_out[c + 0], bo1 = b_out[c + 1];
    float bo2 = b_out[c + 2], bo3 = b_out[c + 3];
    #pragma unroll
    for (int i = 0; i < 4; i++) {
        int r = r0 + tr * 4 + i;
        float4 v;
        v.x = fminf(fmaxf(acc[i][0] + bo0, -20.0f), 20.0f);
        v.y = fminf(fmaxf(acc[i][1] + bo1, -20.0f), 20.0f);
        v.z = fminf(fmaxf(acc[i][2] + bo2, -20.0f), 20.0f);
        v.w = fminf(fmaxf(acc[i][3] + bo3, -20.0f), 20.0f);
        *(float4*)(out_list + (size_t)r * NOUT + c) = v;
    }
}

// ---------------- launch ------------------------------------------------------
extern "C" void kernel_launch(void* const* d_in, const int* in_sizes, int n_in,
                              void* d_out, int out_size) {
    const float* x        = (const float*)d_in[0]; // [B,T,NIN]
    const float* hidden0  = (const float*)d_in[1]; // [B,H]
    const float* noise    = (const float*)d_in[2]; // [T,B,H]
    const float* w_in_w   = (const float*)d_in[3]; // [H,NIN]
    const float* w_in_b   = (const float*)d_in[4]; // [H]
    const float* w_hh_w   = (const float*)d_in[5]; // [H,H]
    const float* w_hh_b   = (const float*)d_in[6]; // [H]
    const float* w_out_w  = (const float*)d_in[7]; // [NOUT,H]
    const float* w_out_b  = (const float*)d_in[8]; // [NOUT]

    float* out      = (float*)d_out;
    float* hid_list = out;                                        // [B,T,H]
    float* out_list = out + (size_t)B_SZ * T_LEN * H_SZ;          // [B,T,NOUT]
    float* h_final  = out_list + (size_t)B_SZ * T_LEN * NOUT;     // [B,H]

    init_kernel<<<(B_SZ * H_SZ + 255) / 256, 256>>>(hidden0);
    pre_kernel<<<dim3((T_LEN * B_SZ) / 64, H_SZ / 64), 256>>>(
        x, noise, w_in_w, w_in_b, w_hh_b);
    rnn_kernel<<<GRID_RNN, 256>>>(hid_list, h_final, w_hh_w);
    post_kernel<<<dim3((B_SZ * T_LEN) / 64, NOUT / 64), 256>>>(
        hid_list, w_out_w, w_out_b, out_list);
}

// round 5
// speedup vs baseline: 1.9531x; 1.9531x over previous
#include <cuda_runtime.h>
#include <cuda_bf16.h>
#include <math.h>
#include <stdint.h>

#define T_LEN   512
#define B_SZ    128
#define H_SZ    1024
#define NIN     128
#define NOUT    128
#define ALPHA_F 0.25f
#define LEAK_F  0.75f
#define NSCALE  0.025f
#define GRID_RNN 128

// SMEM layout for rnn kernel (bytes). 64 rows x 264 bf16 (528B pitch) per matrix.
#define PITCH  528
#define A_HI   0
#define A_LO   33792
#define B_HI   67584
#define B_LO   101376
#define SM_ALLOC 135168

// ---------------- device scratch ----------------
__device__ float g_c[(size_t)T_LEN * B_SZ * H_SZ];   // alpha*(xWin+b_in+b_hh)+scaled noise
__device__ float g_h[B_SZ * H_SZ];                   // current hidden (fp32)
__device__ __nv_bfloat16 g_a_hi[B_SZ * H_SZ];        // tanh(h) split hi
__device__ __nv_bfloat16 g_a_lo[B_SZ * H_SZ];        // tanh(h) split lo
__device__ float g_p[4 * B_SZ * H_SZ];               // split-K partials
__device__ unsigned g_bar_count;
__device__ unsigned g_bar_release;

// bf16 mma m16n8k16, fp32 accum (baseline PTX, works on compute_103)
__device__ __forceinline__ void mma_bf16(float& c0, float& c1, float& c2, float& c3,
                                         uint32_t a0, uint32_t a1, uint32_t a2, uint32_t a3,
                                         uint32_t b0, uint32_t b1) {
    asm volatile(
        "mma.sync.aligned.m16n8k16.row.col.f32.bf16.bf16.f32 "
        "{%0,%1,%2,%3}, {%4,%5,%6,%7}, {%8,%9}, {%0,%1,%2,%3};"
        : "+f"(c0), "+f"(c1), "+f"(c2), "+f"(c3)
        : "r"(a0), "r"(a1), "r"(a2), "r"(a3), "r"(b0), "r"(b1));
}

__device__ __forceinline__ uint32_t smem_u32(const void* p) {
    uint32_t a;
    asm("{ .reg .u64 t; cvta.to.shared.u64 t, %1; cvt.u32.u64 %0, t; }" : "=r"(a) : "l"(p));
    return a;
}

// ---------------- init ----------------
__global__ void init_kernel(const float* __restrict__ hidden) {
    int i = blockIdx.x * blockDim.x + threadIdx.x;
    if (i == 0) { g_bar_count = 0u; g_bar_release = 0u; }
    if (i < B_SZ * H_SZ) {
        float h = hidden[i];
        g_h[i] = h;
        float t = tanhf(h);
        __nv_bfloat16 hi = __float2bfloat16(t);
        g_a_hi[i] = hi;
        g_a_lo[i] = __float2bfloat16(t - __bfloat162float(hi));
    }
}

// ---------------- pre: c[t,b,h] = a*(x@Win^T + b_in + b_hh) + 0.025*noise ---
__global__ void __launch_bounds__(256) pre_kernel(
    const float* __restrict__ x, const float* __restrict__ noise,
    const float* __restrict__ w_in, const float* __restrict__ b_in,
    const float* __restrict__ b_hh)
{
    __shared__ float As[16][68];
    __shared__ float Bs[16][68];
    int tid = threadIdx.x;
    int tr = tid >> 4, tc = tid & 15;
    int lr = tid >> 2, lk = (tid & 3) * 4;
    int r0 = blockIdx.x * 64, c0 = blockIdx.y * 64;
    float acc[4][4] = {};
    int rA = r0 + lr, tt = rA >> 7, bb = rA & 127;
    const float* arow = x + ((size_t)bb * T_LEN + tt) * NIN;
    const float* brow = w_in + (size_t)(c0 + lr) * NIN;
    for (int ko = 0; ko < NIN; ko += 16) {
        float4 av = *(const float4*)(arow + ko + lk);
        float4 bv = *(const float4*)(brow + ko + lk);
        __syncthreads();
        As[lk + 0][lr] = av.x; As[lk + 1][lr] = av.y; As[lk + 2][lr] = av.z; As[lk + 3][lr] = av.w;
        Bs[lk + 0][lr] = bv.x; Bs[lk + 1][lr] = bv.y; Bs[lk + 2][lr] = bv.z; Bs[lk + 3][lr] = bv.w;
        __syncthreads();
        #pragma unroll
        for (int kk = 0; kk < 16; kk++) {
            float a[4], b[4];
            *(float4*)a = *(float4*)&As[kk][tr * 4];
            *(float4*)b = *(float4*)&Bs[kk][tc * 4];
            #pragma unroll
            for (int i = 0; i < 4; i++)
                #pragma unroll
                for (int j = 0; j < 4; j++) acc[i][j] = fmaf(a[i], b[j], acc[i][j]);
        }
    }
    int c = c0 + tc * 4;
    float bi0 = b_in[c] + b_hh[c], bi1 = b_in[c + 1] + b_hh[c + 1];
    float bi2 = b_in[c + 2] + b_hh[c + 2], bi3 = b_in[c + 3] + b_hh[c + 3];
    #pragma unroll
    for (int i = 0; i < 4; i++) {
        size_t off = (size_t)(r0 + tr * 4 + i) * H_SZ + c;
        float4 nv = *(const float4*)(noise + off);
        float4 v;
        v.x = ALPHA_F * (acc[i][0] + bi0) + NSCALE * nv.x;
        v.y = ALPHA_F * (acc[i][1] + bi1) + NSCALE * nv.y;
        v.z = ALPHA_F * (acc[i][2] + bi2) + NSCALE * nv.z;
        v.w = ALPHA_F * (acc[i][3] + bi3) + NSCALE * nv.w;
        *(float4*)(g_c + off) = v;
    }
}

// ---------------- grid barrier ----------------
__device__ __forceinline__ void grid_bar(unsigned target) {
    __syncthreads();
    if (threadIdx.x == 0) {
        __threadfence();
        unsigned arrived = atomicAdd(&g_bar_count, 1u) + 1u;
        if (arrived == target * (unsigned)GRID_RNN) {
            __threadfence();
            atomicExch(&g_bar_release, target);
        } else {
            while (*(volatile unsigned*)&g_bar_release < target) __nanosleep(64);
        }
        __threadfence();
    }
    __syncthreads();
}

// ---------------- persistent recurrent kernel (tensor-core phase G) ----------
// 128 CTAs = 4 k-splits x 2 b-tiles x 16 h-tiles. Per step:
//  G: D_part[64,64] += split-bf16 mma over K=256 (A staged SMEM, B resident SMEM)
//  bar; U: elementwise leaky update + tanh-split writeback; bar.
__global__ void __launch_bounds__(256, 1) rnn_kernel(
    float* __restrict__ hid_list, float* __restrict__ h_final,
    const float* __restrict__ w_hh)
{
    extern __shared__ char sm[];
    const int cta = blockIdx.x;
    const int ks = cta & 3;
    const int bt = (cta >> 2) & 1;
    const int ht = cta >> 3;
    const int tid = threadIdx.x;
    const int r0 = bt * 64, c0 = ht * 64, k0 = ks * 256;

    // ---- convert resident weight slice to bf16 hi/lo (once) ----
    for (int e = tid; e < 64 * 256; e += 256) {
        int n = e >> 8, k = e & 255;
        float w = w_hh[(size_t)(c0 + n) * H_SZ + k0 + k];
        __nv_bfloat16 wh = __float2bfloat16(w);
        __nv_bfloat16 wl = __float2bfloat16(w - __bfloat162float(wh));
        *(__nv_bfloat16*)(sm + B_HI + n * PITCH + k * 2) = wh;
        *(__nv_bfloat16*)(sm + B_LO + n * PITCH + k * 2) = wl;
    }
    __syncthreads();

    const int wid = tid >> 5, lane = tid & 31;
    const int wm = (wid & 3) * 16;        // warp M offset within 64
    const int wn = (wid >> 2) * 32;       // warp N offset within 64
    const int gq = lane >> 2;             // group id 0..7
    const int q  = lane & 3;

    float* pout = g_p + (size_t)ks * (B_SZ * H_SZ);
    const char* pAh = sm + A_HI + (wm + gq) * PITCH + q * 4;
    const char* pAl = sm + A_LO + (wm + gq) * PITCH + q * 4;
    const char* pBh = sm + B_HI + (wn + gq) * PITCH + q * 4;
    const char* pBl = sm + B_LO + (wn + gq) * PITCH + q * 4;

    const int e  = cta * 1024 + tid * 4;  // update-phase ownership
    const int eb = e >> 10, eh = e & 1023;
    unsigned epoch = 0;

    for (int t = 0; t < T_LEN; t++) {
        // ---- stage A slice (64 rows x 256 cols, hi+lo) into SMEM ----
        #pragma unroll
        for (int i = 0; i < 8; i++) {
            int idx = i * 256 + tid;       // 0..2047
            int r = idx >> 5, cc = idx & 31;
            size_t goff = (size_t)(r0 + r) * 2048 + (size_t)k0 * 2 + cc * 16;
            uint4 vh = __ldcg((const uint4*)((const char*)g_a_hi + goff));
            uint4 vl = __ldcg((const uint4*)((const char*)g_a_lo + goff));
            *(uint4*)(sm + A_HI + r * PITCH + cc * 16) = vh;
            *(uint4*)(sm + A_LO + r * PITCH + cc * 16) = vl;
        }
        __syncthreads();

        // ---- split-bf16 tensor GEMM: acc = Ahi*Bhi + Ahi*Blo + Alo*Bhi ----
        float acc[4][4] = {};
        #pragma unroll
        for (int kk = 0; kk < 16; kk++) {
            const int kb = kk * 32;        // 16 bf16 = 32 bytes per k-step
            uint32_t ah0 = *(const uint32_t*)(pAh + kb);
            uint32_t ah1 = *(const uint32_t*)(pAh + 8 * PITCH + kb);
            uint32_t ah2 = *(const uint32_t*)(pAh + kb + 16);
            uint32_t ah3 = *(const uint32_t*)(pAh + 8 * PITCH + kb + 16);
            uint32_t al0 = *(const uint32_t*)(pAl + kb);
            uint32_t al1 = *(const uint32_t*)(pAl + 8 * PITCH + kb);
            uint32_t al2 = *(const uint32_t*)(pAl + kb + 16);
            uint32_t al3 = *(const uint32_t*)(pAl + 8 * PITCH + kb + 16);
            #pragma unroll
            for (int j = 0; j < 4; j++) {
                uint32_t bh0 = *(const uint32_t*)(pBh + j * 8 * PITCH + kb);
                uint32_t bh1 = *(const uint32_t*)(pBh + j * 8 * PITCH + kb + 16);
                uint32_t bl0 = *(const uint32_t*)(pBl + j * 8 * PITCH + kb);
                uint32_t bl1 = *(const uint32_t*)(pBl + j * 8 * PITCH + kb + 16);
                mma_bf16(acc[j][0], acc[j][1], acc[j][2], acc[j][3],
                         ah0, ah1, ah2, ah3, bh0, bh1);
                mma_bf16(acc[j][0], acc[j][1], acc[j][2], acc[j][3],
                         ah0, ah1, ah2, ah3, bl0, bl1);
                mma_bf16(acc[j][0], acc[j][1], acc[j][2], acc[j][3],
                         al0, al1, al2, al3, bh0, bh1);
            }
        }
        // write partials: rows r0+wm+gq(+8), cols c0+wn+j*8+q*2(+1)
        #pragma unroll
        for (int j = 0; j < 4; j++) {
            float* pp = pout + (size_t)(r0 + wm + gq) * H_SZ + c0 + wn + j * 8 + q * 2;
            *(float2*)pp = make_float2(acc[j][0], acc[j][1]);
            *(float2*)(pp + 8 * H_SZ) = make_float2(acc[j][2], acc[j][3]);
        }

        grid_bar(++epoch);

        // ---- update phase: h' = 0.75h + 0.25*sum(partials) + c[t] ----
        {
            float4 p0 = *(const float4*)(g_p + e);
            float4 p1 = *(const float4*)(g_p + 1 * B_SZ * H_SZ + e);
            float4 p2 = *(const float4*)(g_p + 2 * B_SZ * H_SZ + e);
            float4 p3 = *(const float4*)(g_p + 3 * B_SZ * H_SZ + e);
            float4 hc = *(const float4*)(g_h + e);
            float4 cv = *(const float4*)(g_c + (size_t)t * (B_SZ * H_SZ) + e);
            float4 hn;
            hn.x = LEAK_F * hc.x + ALPHA_F * (p0.x + p1.x + p2.x + p3.x) + cv.x;
            hn.y = LEAK_F * hc.y + ALPHA_F * (p0.y + p1.y + p2.y + p3.y) + cv.y;
            hn.z = LEAK_F * hc.z + ALPHA_F * (p0.z + p1.z + p2.z + p3.z) + cv.z;
            hn.w = LEAK_F * hc.w + ALPHA_F * (p0.w + p1.w + p2.w + p3.w) + cv.w;
            *(float4*)(g_h + e) = hn;
            *(float4*)(hid_list + ((size_t)eb * T_LEN + t) * H_SZ + eh) = hn;
            if (t == T_LEN - 1) *(float4*)(h_final + e) = hn;

            float t0 = tanhf(hn.x), t1 = tanhf(hn.y), t2 = tanhf(hn.z), t3 = tanhf(hn.w);
            __nv_bfloat16 h0 = __float2bfloat16(t0), h1 = __float2bfloat16(t1);
            __nv_bfloat16 h2 = __float2bfloat16(t2), h3 = __float2bfloat16(t3);
            __nv_bfloat16 l0 = __float2bfloat16(t0 - __bfloat162float(h0));
            __nv_bfloat16 l1 = __float2bfloat16(t1 - __bfloat162float(h1));
            __nv_bfloat16 l2 = __float2bfloat16(t2 - __bfloat162float(h2));
            __nv_bfloat16 l3 = __float2bfloat16(t3 - __bfloat162float(h3));
            uint2 hw, lw;
            hw.x = (uint32_t)__bfloat16_as_ushort(h0) | ((uint32_t)__bfloat16_as_ushort(h1) << 16);
            hw.y = (uint32_t)__bfloat16_as_ushort(h2) | ((uint32_t)__bfloat16_as_ushort(h3) << 16);
            lw.x = (uint32_t)__bfloat16_as_ushort(l0) | ((uint32_t)__bfloat16_as_ushort(l1) << 16);
            lw.y = (uint32_t)__bfloat16_as_ushort(l2) | ((uint32_t)__bfloat16_as_ushort(l3) << 16);
            *(uint2*)((char*)g_a_hi + (size_t)e * 2) = hw;
            *(uint2*)((char*)g_a_lo + (size_t)e * 2) = lw;
        }

        grid_bar(++epoch);
    }
}

// ---------------- post: out = clip(hid @ Wout^T + b_out) --------------------
__global__ void __launch_bounds__(256) post_kernel(
    const float* __restrict__ hid_list, const float* __restrict__ w_out,
    const float* __restrict__ b_out, float* __restrict__ out_list)
{
    __shared__ float As[16][68];
    __shared__ float Bs[16][68];
    int tid = threadIdx.x;
    int tr = tid >> 4, tc = tid & 15;
    int lr = tid >> 2, lk = (tid & 3) * 4;
    int r0 = blockIdx.x * 64, c0 = blockIdx.y * 64;
    float acc[4][4] = {};
    const float* arow = hid_list + (size_t)(r0 + lr) * H_SZ;
    const float* brow = w_out + (size_t)(c0 + lr) * H_SZ;
    for (int ko = 0; ko < H_SZ; ko += 16) {
        float4 av = *(const float4*)(arow + ko + lk);
        float4 bv = *(const float4*)(brow + ko + lk);
        __syncthreads();
        As[lk + 0][lr] = av.x; As[lk + 1][lr] = av.y; As[lk + 2][lr] = av.z; As[lk + 3][lr] = av.w;
        Bs[lk + 0][lr] = bv.x; Bs[lk + 1][lr] = bv.y; Bs[lk + 2][lr] = bv.z; Bs[lk + 3][lr] = bv.w;
        __syncthreads();
        #pragma unroll
        for (int kk = 0; kk < 16; kk++) {
            float a[4], b[4];
            *(float4*)a = *(float4*)&As[kk][tr * 4];
            *(float4*)b = *(float4*)&Bs[kk][tc * 4];
            #pragma unroll
            for (int i = 0; i < 4; i++)
                #pragma unroll
                for (int j = 0; j < 4; j++) acc[i][j] = fmaf(a[i], b[j], acc[i][j]);
        }
    }
    int c = c0 + tc * 4;
    float bo0 = b_out[c], bo1 = b_out[c + 1], bo2 = b_out[c + 2], bo3 = b_out[c + 3];
    #pragma unroll
    for (int i = 0; i < 4; i++) {
        int r = r0 + tr * 4 + i;
        float4 v;
        v.x = fminf(fmaxf(acc[i][0] + bo0, -20.0f), 20.0f);
        v.y = fminf(fmaxf(acc[i][1] + bo1, -20.0f), 20.0f);
        v.z = fminf(fmaxf(acc[i][2] + bo2, -20.0f), 20.0f);
        v.w = fminf(fmaxf(acc[i][3] + bo3, -20.0f), 20.0f);
        *(float4*)(out_list + (size_t)r * NOUT + c) = v;
    }
}

extern "C" void kernel_launch(void* const* d_in, const int* in_sizes, int n_in,
                              void* d_out, int out_size) {
    const float* x       = (const float*)d_in[0];
    const float* hidden0 = (const float*)d_in[1];
    const float* noise   = (const float*)d_in[2];
    const float* w_in_w  = (const float*)d_in[3];
    const float* w_in_b  = (const float*)d_in[4];
    const float* w_hh_w  = (const float*)d_in[5];
    const float* w_hh_b  = (const float*)d_in[6];
    const float* w_out_w = (const float*)d_in[7];
    const float* w_out_b = (const float*)d_in[8];

    float* out      = (float*)d_out;
    float* hid_list = out;
    float* out_list = out + (size_t)B_SZ * T_LEN * H_SZ;
    float* h_final  = out_list + (size_t)B_SZ * T_LEN * NOUT;

    cudaFuncSetAttribute(rnn_kernel, cudaFuncAttributeMaxDynamicSharedMemorySize, SM_ALLOC);
    init_kernel<<<(B_SZ * H_SZ + 255) / 256, 256>>>(hidden0);
    pre_kernel<<<dim3((T_LEN * B_SZ) / 64, H_SZ / 64), 256>>>(x, noise, w_in_w, w_in_b, w_hh_b);
    rnn_kernel<<<GRID_RNN, 256, SM_ALLOC>>>(hid_list, h_final, w_hh_w);
    post_kernel<<<dim3((B_SZ * T_LEN) / 64, NOUT / 64), 256>>>(hid_list, w_out_w, w_out_b, out_list);
}